// round 1
// baseline (speedup 1.0000x reference)
#include <cuda_runtime.h>
#include <math.h>

#define BB 8
#define SS 256
#define NNODE 64
#define DD 512
#define VV 32000
#define M2 (BB * SS)   /* 2048 */
#define LN_EPS 1e-5f

// ---------------- scratch (static device globals; no allocation) ----------------
__device__ __align__(16) float g_Xg[M2 * DD];          // 4 MB  x@Wg_top + bg
__device__ __align__(16) float g_Xu[M2 * DD];          // 4 MB  x@Wu_top + bu
__device__ __align__(16) float g_nodes[2][BB * NNODE * DD]; // 2x1 MB ping-pong state
__device__ __align__(16) float g_cons[M2 * DD];        // 4 MB  consensus [B,S,D]
__device__ __align__(16) float g_ln[M2 * DD];          // 4 MB  layernorm(consensus)

// ---------------- init: nodes0[b,n,:] = manifold[n,:] ----------------
__global__ void init_nodes_kernel(const float* __restrict__ mani) {
    int r = blockIdx.x;          // 0..511 = b*64+n
    int n = r & 63;
    const float* src = mani + (size_t)n * DD;
    float* dst = g_nodes[0] + (size_t)r * DD;
    dst[threadIdx.x]       = src[threadIdx.x];
    dst[threadIdx.x + 256] = src[threadIdx.x + 256];
}

// ---------------- precompute: Xg/Xu = emb[idx] @ W_top + bias ----------------
// grid (16 col-tiles of 32, 32 row-tiles of 64), 256 threads
__global__ __launch_bounds__(256) void precompute_kernel(
    const int* __restrict__ idx, const float* __restrict__ emb,
    const float* __restrict__ Wg, const float* __restrict__ bg,
    const float* __restrict__ Wu, const float* __restrict__ bu)
{
    __shared__ float As[16][68];
    __shared__ float Wgs[16][32];
    __shared__ float Wus[16][32];
    __shared__ int   sidx[64];

    int tid = threadIdx.x;
    int m0 = blockIdx.y * 64;
    int n0 = blockIdx.x * 32;
    if (tid < 64) sidx[tid] = idx[m0 + tid];
    __syncthreads();

    int lm = tid >> 2, lkq = tid & 3;     // A loader: row lm, float4 group lkq
    int lwk = tid >> 4, lwn = tid & 15;   // W loader: row lwk, float2 col lwn
    int ty = tid >> 4, tx = tid & 15;     // compute: rows ty*4.., cols tx*2..

    const float* Arow = emb + (size_t)sidx[lm] * DD + lkq * 4;
    const float* Grow = Wg + (size_t)lwk * DD + n0 + lwn * 2;
    const float* Urow = Wu + (size_t)lwk * DD + n0 + lwn * 2;

    float accg[4][2] = {{0.f,0.f},{0.f,0.f},{0.f,0.f},{0.f,0.f}};
    float accu[4][2] = {{0.f,0.f},{0.f,0.f},{0.f,0.f},{0.f,0.f}};

    float4 pa = *(const float4*)Arow;
    float2 pg = *(const float2*)Grow;
    float2 pu = *(const float2*)Urow;

    for (int kt = 0; kt < 32; ++kt) {
        As[lkq*4+0][lm] = pa.x; As[lkq*4+1][lm] = pa.y;
        As[lkq*4+2][lm] = pa.z; As[lkq*4+3][lm] = pa.w;
        *(float2*)&Wgs[lwk][lwn*2] = pg;
        *(float2*)&Wus[lwk][lwn*2] = pu;
        __syncthreads();
        if (kt < 31) {
            int k0 = (kt + 1) * 16;
            pa = *(const float4*)(Arow + k0);
            pg = *(const float2*)(Grow + (size_t)k0 * DD);
            pu = *(const float2*)(Urow + (size_t)k0 * DD);
        }
        #pragma unroll
        for (int kk = 0; kk < 16; ++kk) {
            float4 a = *(const float4*)&As[kk][ty*4];
            float2 wg = *(const float2*)&Wgs[kk][tx*2];
            float2 wu = *(const float2*)&Wus[kk][tx*2];
            float ar[4] = {a.x, a.y, a.z, a.w};
            #pragma unroll
            for (int i = 0; i < 4; ++i) {
                accg[i][0] = fmaf(ar[i], wg.x, accg[i][0]);
                accg[i][1] = fmaf(ar[i], wg.y, accg[i][1]);
                accu[i][0] = fmaf(ar[i], wu.x, accu[i][0]);
                accu[i][1] = fmaf(ar[i], wu.y, accu[i][1]);
            }
        }
        __syncthreads();
    }

    int col = n0 + tx * 2;
    float bg0 = bg[col], bg1 = bg[col + 1];
    float bu0 = bu[col], bu1 = bu[col + 1];
    #pragma unroll
    for (int i = 0; i < 4; ++i) {
        size_t r = (size_t)(m0 + ty * 4 + i) * DD + col;
        g_Xg[r]     = accg[i][0] + bg0;
        g_Xg[r + 1] = accg[i][1] + bg1;
        g_Xu[r]     = accu[i][0] + bu0;
        g_Xu[r + 1] = accu[i][1] + bu1;
    }
}

// ---------------- one recurrence step ----------------
// grid (16 col-tiles of 32, 8 batches), 256 threads. Row tile = the 64 nodes of batch b.
__global__ __launch_bounds__(256) void step_kernel(
    const float* __restrict__ Wg, const float* __restrict__ Wu, int t)
{
    __shared__ float As[16][68];
    __shared__ float Wgs[16][32];
    __shared__ float Wus[16][32];
    __shared__ float part[16][32];

    const float* nin  = g_nodes[t & 1];
    float*       nout = g_nodes[(t + 1) & 1];
    const float* WgB = Wg + (size_t)DD * DD;   // bottom half rows (nodes part)
    const float* WuB = Wu + (size_t)DD * DD;

    int tid = threadIdx.x;
    int b = blockIdx.y;
    int n0 = blockIdx.x * 32;
    int m0 = b * 64;

    int lm = tid >> 2, lkq = tid & 3;
    int lwk = tid >> 4, lwn = tid & 15;
    int ty = tid >> 4, tx = tid & 15;

    const float* Arow = nin + (size_t)(m0 + lm) * DD + lkq * 4;
    const float* Grow = WgB + (size_t)lwk * DD + n0 + lwn * 2;
    const float* Urow = WuB + (size_t)lwk * DD + n0 + lwn * 2;

    float accg[4][2] = {{0.f,0.f},{0.f,0.f},{0.f,0.f},{0.f,0.f}};
    float accu[4][2] = {{0.f,0.f},{0.f,0.f},{0.f,0.f},{0.f,0.f}};

    float4 pa = *(const float4*)Arow;
    float2 pg = *(const float2*)Grow;
    float2 pu = *(const float2*)Urow;

    for (int kt = 0; kt < 32; ++kt) {
        As[lkq*4+0][lm] = pa.x; As[lkq*4+1][lm] = pa.y;
        As[lkq*4+2][lm] = pa.z; As[lkq*4+3][lm] = pa.w;
        *(float2*)&Wgs[lwk][lwn*2] = pg;
        *(float2*)&Wus[lwk][lwn*2] = pu;
        __syncthreads();
        if (kt < 31) {
            int k0 = (kt + 1) * 16;
            pa = *(const float4*)(Arow + k0);
            pg = *(const float2*)(Grow + (size_t)k0 * DD);
            pu = *(const float2*)(Urow + (size_t)k0 * DD);
        }
        #pragma unroll
        for (int kk = 0; kk < 16; ++kk) {
            float4 a = *(const float4*)&As[kk][ty*4];
            float2 wg = *(const float2*)&Wgs[kk][tx*2];
            float2 wu = *(const float2*)&Wus[kk][tx*2];
            float ar[4] = {a.x, a.y, a.z, a.w};
            #pragma unroll
            for (int i = 0; i < 4; ++i) {
                accg[i][0] = fmaf(ar[i], wg.x, accg[i][0]);
                accg[i][1] = fmaf(ar[i], wg.y, accg[i][1]);
                accu[i][0] = fmaf(ar[i], wu.x, accu[i][0]);
                accu[i][1] = fmaf(ar[i], wu.y, accu[i][1]);
            }
        }
        __syncthreads();
    }

    // epilogue: gate/cand nonlinearity, state update, per-batch consensus
    int col = n0 + tx * 2;
    size_t xoff = (size_t)(b * SS + t) * DD + col;
    float xg0 = g_Xg[xoff], xg1 = g_Xg[xoff + 1];
    float xu0 = g_Xu[xoff], xu1 = g_Xu[xoff + 1];
    float cs0 = 0.f, cs1 = 0.f;
    #pragma unroll
    for (int i = 0; i < 4; ++i) {
        size_t rg = (size_t)(m0 + ty * 4 + i) * DD + col;
        float o0 = nin[rg], o1 = nin[rg + 1];
        float g0 = 1.f / (1.f + expf(-(accg[i][0] + xg0)));
        float g1 = 1.f / (1.f + expf(-(accg[i][1] + xg1)));
        float c0 = tanhf(accu[i][0] + xu0);
        float c1 = tanhf(accu[i][1] + xu1);
        float v0 = g0 * c0 + (1.f - g0) * o0;
        float v1 = g1 * c1 + (1.f - g1) * o1;
        nout[rg] = v0; nout[rg + 1] = v1;
        cs0 += v0; cs1 += v1;
    }
    part[ty][tx*2]     = cs0;
    part[ty][tx*2 + 1] = cs1;
    __syncthreads();
    if (tid < 32) {
        float s = 0.f;
        #pragma unroll
        for (int p = 0; p < 16; ++p) s += part[p][tid];
        g_cons[(size_t)(b * SS + t) * DD + n0 + tid] = s * (1.f / 64.f);
    }
}

// ---------------- layernorm over consensus rows ----------------
__device__ __forceinline__ float warp_sum(float v) {
    v += __shfl_xor_sync(0xffffffffu, v, 16);
    v += __shfl_xor_sync(0xffffffffu, v, 8);
    v += __shfl_xor_sync(0xffffffffu, v, 4);
    v += __shfl_xor_sync(0xffffffffu, v, 2);
    v += __shfl_xor_sync(0xffffffffu, v, 1);
    return v;
}

__global__ __launch_bounds__(128) void ln_kernel(
    const float* __restrict__ lw, const float* __restrict__ lb)
{
    int r = blockIdx.x, tid = threadIdx.x;
    const float* x = g_cons + (size_t)r * DD;
    float4 v = *(const float4*)(x + tid * 4);
    __shared__ float red[4];

    float s = v.x + v.y + v.z + v.w;
    s = warp_sum(s);
    if ((tid & 31) == 0) red[tid >> 5] = s;
    __syncthreads();
    float mu = (red[0] + red[1] + red[2] + red[3]) * (1.f / DD);
    __syncthreads();

    float d0 = v.x - mu, d1 = v.y - mu, d2 = v.z - mu, d3 = v.w - mu;
    float ss = d0*d0 + d1*d1 + d2*d2 + d3*d3;
    ss = warp_sum(ss);
    if ((tid & 31) == 0) red[tid >> 5] = ss;
    __syncthreads();
    float var = (red[0] + red[1] + red[2] + red[3]) * (1.f / DD);
    float inv = rsqrtf(var + LN_EPS);

    float4 w = *(const float4*)(lw + tid * 4);
    float4 bb = *(const float4*)(lb + tid * 4);
    float4 o;
    o.x = d0 * inv * w.x + bb.x;
    o.y = d1 * inv * w.y + bb.y;
    o.z = d2 * inv * w.z + bb.z;
    o.w = d3 * inv * w.w + bb.w;
    *(float4*)(g_ln + (size_t)r * DD + tid * 4) = o;
}

// ---------------- output head: logits = ln @ Wh + bh ----------------
// grid (500 col-tiles of 64, 32 row-tiles of 64), 256 threads, 4x4 microtiles
__global__ __launch_bounds__(256) void out_gemm_kernel(
    const float* __restrict__ Wh, const float* __restrict__ bh,
    float* __restrict__ out)
{
    __shared__ float As[16][68];
    __shared__ float Bs[16][64];

    int tid = threadIdx.x;
    int n0 = blockIdx.x * 64;
    int m0 = blockIdx.y * 64;

    int lm = tid >> 2, lkq = tid & 3;
    int lwk = tid >> 4, lwn = tid & 15;
    int ty = tid >> 4, tx = tid & 15;

    const float* Arow = g_ln + (size_t)(m0 + lm) * DD + lkq * 4;
    const float* Brow = Wh + (size_t)lwk * VV + n0 + lwn * 4;

    float acc[4][4];
    #pragma unroll
    for (int i = 0; i < 4; ++i)
        #pragma unroll
        for (int j = 0; j < 4; ++j) acc[i][j] = 0.f;

    float4 pa = *(const float4*)Arow;
    float4 pb = *(const float4*)Brow;

    for (int kt = 0; kt < 32; ++kt) {
        As[lkq*4+0][lm] = pa.x; As[lkq*4+1][lm] = pa.y;
        As[lkq*4+2][lm] = pa.z; As[lkq*4+3][lm] = pa.w;
        *(float4*)&Bs[lwk][lwn*4] = pb;
        __syncthreads();
        if (kt < 31) {
            int k0 = (kt + 1) * 16;
            pa = *(const float4*)(Arow + k0);
            pb = *(const float4*)(Brow + (size_t)k0 * VV);
        }
        #pragma unroll
        for (int kk = 0; kk < 16; ++kk) {
            float4 a = *(const float4*)&As[kk][ty*4];
            float4 b = *(const float4*)&Bs[kk][tx*4];
            float ar[4] = {a.x, a.y, a.z, a.w};
            float br[4] = {b.x, b.y, b.z, b.w};
            #pragma unroll
            for (int i = 0; i < 4; ++i)
                #pragma unroll
                for (int j = 0; j < 4; ++j)
                    acc[i][j] = fmaf(ar[i], br[j], acc[i][j]);
        }
        __syncthreads();
    }

    float4 b4 = *(const float4*)(bh + n0 + tx * 4);
    #pragma unroll
    for (int i = 0; i < 4; ++i) {
        size_t row = (size_t)(m0 + ty * 4 + i);
        float4 o;
        o.x = acc[i][0] + b4.x;
        o.y = acc[i][1] + b4.y;
        o.z = acc[i][2] + b4.z;
        o.w = acc[i][3] + b4.w;
        *(float4*)(out + row * VV + n0 + tx * 4) = o;
    }
}

// ---------------- launch ----------------
extern "C" void kernel_launch(void* const* d_in, const int* in_sizes, int n_in,
                              void* d_out, int out_size)
{
    const int*   idx  = (const int*)  d_in[0];
    const float* emb  = (const float*)d_in[1];
    const float* mani = (const float*)d_in[2];
    const float* Wg   = (const float*)d_in[3];
    const float* bg   = (const float*)d_in[4];
    const float* Wu   = (const float*)d_in[5];
    const float* bu   = (const float*)d_in[6];
    const float* lw   = (const float*)d_in[7];
    const float* lb   = (const float*)d_in[8];
    const float* Wh   = (const float*)d_in[9];
    const float* bh   = (const float*)d_in[10];
    float* out = (float*)d_out;

    init_nodes_kernel<<<512, 256>>>(mani);
    precompute_kernel<<<dim3(16, 32), 256>>>(idx, emb, Wg, bg, Wu, bu);
    for (int t = 0; t < SS; ++t)
        step_kernel<<<dim3(16, 8), 256>>>(Wg, Wu, t);
    ln_kernel<<<M2, 128>>>(lw, lb);
    out_gemm_kernel<<<dim3(500, 32), 256>>>(Wh, bh, out);
}